// round 7
// baseline (speedup 1.0000x reference)
#include <cuda_runtime.h>
#include <cuda_bf16.h>
#include <math_constants.h>
#include <cstdint>

// Problem constants
#define BATCH 2
#define SEQ   2048
#define CH    1024
#define HEADS 16
#define DH    64
#define MROWS (BATCH*SEQ)   // 4096

// ---------------------------------------------------------------------------
// Device scratch
// ---------------------------------------------------------------------------
__device__ float g_qkv[(size_t)MROWS * 3 * CH];
__device__ __nv_bfloat16 g_Ahi[(size_t)MROWS * CH];
__device__ __nv_bfloat16 g_Alo[(size_t)MROWS * CH];
__device__ __nv_bfloat16 g_BQhi[(size_t)(3*CH) * CH];
__device__ __nv_bfloat16 g_BQlo[(size_t)(3*CH) * CH];
__device__ __nv_bfloat16 g_BPhi[(size_t)CH * CH];
__device__ __nv_bfloat16 g_BPlo[(size_t)CH * CH];

// ---------------------------------------------------------------------------
// Helpers
// ---------------------------------------------------------------------------
__device__ __forceinline__ uint32_t smem_u32(const void* p) {
    uint32_t a;
    asm("{ .reg .u64 t; cvta.to.shared.u64 t, %1; cvt.u32.u64 %0, t; }"
        : "=r"(a) : "l"(p));
    return a;
}

#define SWZ128(o) ((o) ^ (((o) >> 3) & 0x70))

#define CP_ASYNC16(dst_u32, src_ptr) \
    asm volatile("cp.async.cg.shared.global [%0], [%1], 16;\n" \
                 :: "r"(dst_u32), "l"(src_ptr))
#define CP_COMMIT() asm volatile("cp.async.commit_group;\n" ::: "memory")
#define CP_WAIT0()  asm volatile("cp.async.wait_group 0;\n" ::: "memory")
#define CP_WAIT1()  asm volatile("cp.async.wait_group 1;\n" ::: "memory")

#define LDSM_X4(r0, r1, r2, r3, addr) \
    asm volatile("ldmatrix.sync.aligned.m8n8.x4.shared.b16 {%0,%1,%2,%3}, [%4];" \
                 : "=r"(r0), "=r"(r1), "=r"(r2), "=r"(r3) : "r"(addr))
#define LDSM_X2(r0, r1, addr) \
    asm volatile("ldmatrix.sync.aligned.m8n8.x2.shared.b16 {%0,%1}, [%2];" \
                 : "=r"(r0), "=r"(r1) : "r"(addr))
#define MMA16816(d, a0, a1, a2, a3, b0, b1) \
    asm volatile("mma.sync.aligned.m16n8k16.row.col.f32.bf16.bf16.f32 " \
                 "{%0,%1,%2,%3},{%4,%5,%6,%7},{%8,%9},{%0,%1,%2,%3};" \
                 : "+f"((d)[0]), "+f"((d)[1]), "+f"((d)[2]), "+f"((d)[3]) \
                 : "r"(a0), "r"(a1), "r"(a2), "r"(a3), "r"(b0), "r"(b1))

// ---------------------------------------------------------------------------
// bf16x3 GEMM: C[M,N] = (Ahi+Alo)[M,K] @ (Bhi+Blo)[N,K]^T + bias
// EXACT R3 configuration (fastest measured): CTA 128x128, KC=64, 2-stage
// cp.async double buffer, 8 warps in 2(M) x 4(N) grid, 64x32 warp tiles,
// X2 B-loads, B-operand-shared MMA ordering.
// ---------------------------------------------------------------------------
#define KC 64
#define STAGE_BYTES 65536
#define GEMM_SMEM (1024 + 2 * STAGE_BYTES)

__device__ __forceinline__ void load_chunk_tiles(
    const __nv_bfloat16* __restrict__ Ah, const __nv_bfloat16* __restrict__ Al,
    const __nv_bfloat16* __restrict__ Bh, const __nv_bfloat16* __restrict__ Bl,
    int K, int m0, int n0, int c, uint32_t st, int tid)
{
    #pragma unroll
    for (int t = 0; t < 4; t++) {
        int idx = t * 256 + tid;
        int row = idx >> 3;
        int col = idx & 7;
        uint32_t off = SWZ128(row * 128 + col * 16);
        size_t ga = (size_t)(m0 + row) * K + c * KC + col * 8;
        size_t gb = (size_t)(n0 + row) * K + c * KC + col * 8;
        CP_ASYNC16(st + off,         Ah + ga);
        CP_ASYNC16(st + 16384 + off, Al + ga);
        CP_ASYNC16(st + 32768 + off, Bh + gb);
        CP_ASYNC16(st + 49152 + off, Bl + gb);
    }
}

__global__ __launch_bounds__(256, 1)
void gemm_bf16x3_kernel(const __nv_bfloat16* __restrict__ Ah,
                        const __nv_bfloat16* __restrict__ Al,
                        const __nv_bfloat16* __restrict__ Bh,
                        const __nv_bfloat16* __restrict__ Bl,
                        const float* __restrict__ bias,
                        float* __restrict__ C,
                        int N, int K)
{
    extern __shared__ char smem[];
    const uint32_t sb = smem_u32(smem);
    const uint32_t tiles = (sb + 1023) & ~1023u;
    const int tid  = threadIdx.x;
    const int wid  = tid >> 5;
    const int lane = tid & 31;
    const int m0 = blockIdx.y * 128;
    const int n0 = blockIdx.x * 128;
    const int NCHUNK = K / KC;

    const int warpM = wid >> 2;        // 0..1
    const int warpN = wid & 3;         // 0..3

    float acc[4][4][4];
    #pragma unroll
    for (int mt = 0; mt < 4; mt++)
        #pragma unroll
        for (int nt = 0; nt < 4; nt++)
            #pragma unroll
            for (int e = 0; e < 4; e++) acc[mt][nt][e] = 0.0f;

    // per-lane ldmatrix address components
    const int aRowBase  = warpM * 64 + (lane & 15);
    const int aByteSel  = (lane >> 4) * 16;
    const int bRowBase  = warpN * 32 + (lane & 7);
    const int bByteSel  = ((lane >> 3) & 1) * 16;

    load_chunk_tiles(Ah, Al, Bh, Bl, K, m0, n0, 0, tiles, tid);
    CP_COMMIT();

    for (int c = 0; c < NCHUNK; ++c) {
        if (c + 1 < NCHUNK) {
            load_chunk_tiles(Ah, Al, Bh, Bl, K, m0, n0, c + 1,
                             tiles + ((c + 1) & 1) * STAGE_BYTES, tid);
            CP_COMMIT();
            CP_WAIT1();
        } else {
            CP_WAIT0();
        }
        __syncthreads();

        const uint32_t st  = tiles + (c & 1) * STAGE_BYTES;
        const uint32_t aHi = st;
        const uint32_t aLo = st + 16384;
        const uint32_t bHi = st + 32768;
        const uint32_t bLo = st + 49152;

        #pragma unroll
        for (int kk = 0; kk < 4; kk++) {
            uint32_t bh[4][2], bl[4][2];
            #pragma unroll
            for (int nt = 0; nt < 4; nt++) {
                uint32_t boff = SWZ128((uint32_t)((bRowBase + nt * 8) * 128 + kk * 32 + bByteSel));
                LDSM_X2(bh[nt][0], bh[nt][1], bHi + boff);
                LDSM_X2(bl[nt][0], bl[nt][1], bLo + boff);
            }
            #pragma unroll
            for (int mt = 0; mt < 4; mt++) {
                uint32_t aoff = SWZ128((uint32_t)((aRowBase + mt * 16) * 128 + kk * 32 + aByteSel));
                uint32_t ah0, ah1, ah2, ah3, al0, al1, al2, al3;
                LDSM_X4(ah0, ah1, ah2, ah3, aHi + aoff);
                LDSM_X4(al0, al1, al2, al3, aLo + aoff);
                #pragma unroll
                for (int nt = 0; nt < 4; nt++) {
                    MMA16816(acc[mt][nt], ah0, ah1, ah2, ah3, bh[nt][0], bh[nt][1]);
                    MMA16816(acc[mt][nt], al0, al1, al2, al3, bh[nt][0], bh[nt][1]);
                    MMA16816(acc[mt][nt], ah0, ah1, ah2, ah3, bl[nt][0], bl[nt][1]);
                }
            }
        }
        __syncthreads();
    }

    // epilogue: bias + store (float2 per acc half)
    #pragma unroll
    for (int mt = 0; mt < 4; mt++) {
        int r0 = m0 + warpM * 64 + mt * 16 + (lane >> 2);
        #pragma unroll
        for (int nt = 0; nt < 4; nt++) {
            int c0 = n0 + warpN * 32 + nt * 8 + (lane & 3) * 2;
            float2 bv = *(const float2*)(bias + c0);
            float2 o0 = make_float2(acc[mt][nt][0] + bv.x, acc[mt][nt][1] + bv.y);
            float2 o1 = make_float2(acc[mt][nt][2] + bv.x, acc[mt][nt][3] + bv.y);
            *(float2*)(C + (size_t)r0 * N + c0)       = o0;
            *(float2*)(C + (size_t)(r0 + 8) * N + c0) = o1;
        }
    }
}

// ---------------------------------------------------------------------------
// Split fp32 -> bf16 hi + bf16 residual lo
// ---------------------------------------------------------------------------
__global__ __launch_bounds__(256)
void conv_split_kernel(const float* __restrict__ in,
                       __nv_bfloat16* __restrict__ hi,
                       __nv_bfloat16* __restrict__ lo, int n4)
{
    int i = blockIdx.x * 256 + threadIdx.x;
    if (i >= n4) return;
    float4 v = ((const float4*)in)[i];
    __nv_bfloat16 h0 = __float2bfloat16(v.x);
    __nv_bfloat16 h1 = __float2bfloat16(v.y);
    __nv_bfloat16 h2 = __float2bfloat16(v.z);
    __nv_bfloat16 h3 = __float2bfloat16(v.w);
    __nv_bfloat16 l0 = __float2bfloat16(v.x - __bfloat162float(h0));
    __nv_bfloat16 l1 = __float2bfloat16(v.y - __bfloat162float(h1));
    __nv_bfloat16 l2 = __float2bfloat16(v.z - __bfloat162float(h2));
    __nv_bfloat16 l3 = __float2bfloat16(v.w - __bfloat162float(h3));
    ((__nv_bfloat162*)hi)[2 * i + 0] = __nv_bfloat162(h0, h1);
    ((__nv_bfloat162*)hi)[2 * i + 1] = __nv_bfloat162(h2, h3);
    ((__nv_bfloat162*)lo)[2 * i + 0] = __nv_bfloat162(l0, l1);
    ((__nv_bfloat162*)lo)[2 * i + 1] = __nv_bfloat162(l2, l3);
}

// ---------------------------------------------------------------------------
// Transpose + split: W[K,N] fp32 -> Wt hi/lo [N,K] bf16
// ---------------------------------------------------------------------------
__global__ __launch_bounds__(256)
void conv_transpose_kernel(const float* __restrict__ W,
                           __nv_bfloat16* __restrict__ hi,
                           __nv_bfloat16* __restrict__ lo, int K, int N)
{
    __shared__ float tile[32][33];
    const int n0 = blockIdx.x * 32;
    const int k0 = blockIdx.y * 32;
    const int tx = threadIdx.x & 31;
    const int ty = threadIdx.x >> 5;

    #pragma unroll
    for (int j = ty; j < 32; j += 8)
        tile[j][tx] = W[(size_t)(k0 + j) * N + n0 + tx];
    __syncthreads();

    #pragma unroll
    for (int j = ty; j < 32; j += 8) {
        float v = tile[tx][j];
        __nv_bfloat16 h = __float2bfloat16(v);
        __nv_bfloat16 l = __float2bfloat16(v - __bfloat162float(h));
        size_t o = (size_t)(n0 + j) * K + k0 + tx;
        hi[o] = h;
        lo[o] = l;
    }
}

// ---------------------------------------------------------------------------
// Fenwick sparse attention, fused hi/lo split output.
// Mask row t = {t} U {t-2^k}, <=12 keys. One warp per (b,h,t).
// ---------------------------------------------------------------------------
__global__ __launch_bounds__(256)
void fenwick_attn_kernel(const float* __restrict__ qkv,
                         __nv_bfloat16* __restrict__ outHi,
                         __nv_bfloat16* __restrict__ outLo)
{
    const int warp = threadIdx.x >> 5;
    const int lane = threadIdx.x & 31;
    const int t  = blockIdx.x * 8 + warp;
    const int bh = blockIdx.y;
    const int b = bh >> 4;
    const int h = bh & 15;

    const float scale = 0.125f;
    const size_t rowStride = 3 * CH;
    const float* base = qkv + (size_t)b * SEQ * rowStride;

    const float* qp = base + (size_t)t * rowStride + h * DH;
    const float q0 = qp[lane];
    const float q1 = qp[lane + 32];

    int pos[12];
    int np = 0;
    pos[np++] = t;
    for (int step = 1; t - step >= 0; step <<= 1) pos[np++] = t - step;

    float s[12];
    float m = -CUDART_INF_F;
    for (int i = 0; i < np; i++) {
        const float* kp = base + (size_t)pos[i] * rowStride + CH + h * DH;
        float d = q0 * kp[lane] + q1 * kp[lane + 32];
        #pragma unroll
        for (int off = 16; off; off >>= 1) d += __shfl_xor_sync(0xFFFFFFFFu, d, off);
        d *= scale;
        s[i] = d;
        m = fmaxf(m, d);
    }

    float denom = 0.0f;
    for (int i = 0; i < np; i++) { s[i] = __expf(s[i] - m); denom += s[i]; }
    const float inv = 1.0f / denom;

    float o0 = 0.0f, o1 = 0.0f;
    for (int i = 0; i < np; i++) {
        const float* vp = base + (size_t)pos[i] * rowStride + 2 * CH + h * DH;
        o0 = fmaf(s[i], vp[lane], o0);
        o1 = fmaf(s[i], vp[lane + 32], o1);
    }
    o0 *= inv;
    o1 *= inv;

    const size_t o = ((size_t)b * SEQ + t) * CH + h * DH;
    __nv_bfloat16 h0 = __float2bfloat16(o0);
    __nv_bfloat16 h1 = __float2bfloat16(o1);
    outHi[o + lane]      = h0;
    outHi[o + lane + 32] = h1;
    outLo[o + lane]      = __float2bfloat16(o0 - __bfloat162float(h0));
    outLo[o + lane + 32] = __float2bfloat16(o1 - __bfloat162float(h1));
}

// ---------------------------------------------------------------------------
// Launch
// ---------------------------------------------------------------------------
extern "C" void kernel_launch(void* const* d_in, const int* in_sizes, int n_in,
                              void* d_out, int out_size)
{
    const float* x      = (const float*)d_in[0];
    const float* W_qkv  = (const float*)d_in[1];
    const float* b_qkv  = (const float*)d_in[2];
    const float* W_proj = (const float*)d_in[3];
    const float* b_proj = (const float*)d_in[4];
    float* out = (float*)d_out;

    float *qkv;
    __nv_bfloat16 *Ahi, *Alo, *BQhi, *BQlo, *BPhi, *BPlo;
    cudaGetSymbolAddress((void**)&qkv,  g_qkv);
    cudaGetSymbolAddress((void**)&Ahi,  g_Ahi);
    cudaGetSymbolAddress((void**)&Alo,  g_Alo);
    cudaGetSymbolAddress((void**)&BQhi, g_BQhi);
    cudaGetSymbolAddress((void**)&BQlo, g_BQlo);
    cudaGetSymbolAddress((void**)&BPhi, g_BPhi);
    cudaGetSymbolAddress((void**)&BPlo, g_BPlo);

    cudaFuncSetAttribute(gemm_bf16x3_kernel,
                         cudaFuncAttributeMaxDynamicSharedMemorySize, GEMM_SMEM);

    conv_transpose_kernel<<<dim3(3 * CH / 32, CH / 32), 256>>>(W_qkv, BQhi, BQlo, CH, 3 * CH);
    conv_transpose_kernel<<<dim3(CH / 32, CH / 32), 256>>>(W_proj, BPhi, BPlo, CH, CH);
    conv_split_kernel<<<(MROWS * CH / 4 + 255) / 256, 256>>>(x, Ahi, Alo, MROWS * CH / 4);

    // GEMM1: [4096, 3072] = x @ W_qkv + b_qkv
    gemm_bf16x3_kernel<<<dim3(3 * CH / 128, MROWS / 128), 256, GEMM_SMEM>>>(
        Ahi, Alo, BQhi, BQlo, b_qkv, qkv, 3 * CH, CH);

    // Attention with fused hi/lo split output (overwrites Ahi/Alo)
    fenwick_attn_kernel<<<dim3(SEQ / 8, BATCH * HEADS), 256>>>(qkv, Ahi, Alo);

    // GEMM2: [4096, 1024] = att @ W_proj + b_proj
    gemm_bf16x3_kernel<<<dim3(CH / 128, MROWS / 128), 256, GEMM_SMEM>>>(
        Ahi, Alo, BPhi, BPlo, b_proj, out, CH, CH);
}

// round 8
// speedup vs baseline: 1.1943x; 1.1943x over previous
#include <cuda_runtime.h>
#include <cuda_bf16.h>
#include <math_constants.h>
#include <cstdint>

// Problem constants
#define BATCH 2
#define SEQ   2048
#define CH    1024
#define HEADS 16
#define DH    64
#define MROWS (BATCH*SEQ)   // 4096

// ---------------------------------------------------------------------------
// Device scratch
// ---------------------------------------------------------------------------
__device__ float g_qkv[(size_t)MROWS * 3 * CH];
__device__ __nv_bfloat16 g_Ahi[(size_t)MROWS * CH];
__device__ __nv_bfloat16 g_Alo[(size_t)MROWS * CH];
__device__ __nv_bfloat16 g_BQhi[(size_t)(3*CH) * CH];
__device__ __nv_bfloat16 g_BQlo[(size_t)(3*CH) * CH];
__device__ __nv_bfloat16 g_BPhi[(size_t)CH * CH];
__device__ __nv_bfloat16 g_BPlo[(size_t)CH * CH];

// ---------------------------------------------------------------------------
// Helpers
// ---------------------------------------------------------------------------
__device__ __forceinline__ uint32_t smem_u32(const void* p) {
    uint32_t a;
    asm("{ .reg .u64 t; cvta.to.shared.u64 t, %1; cvt.u32.u64 %0, t; }"
        : "=r"(a) : "l"(p));
    return a;
}

#define SWZ128(o) ((o) ^ (((o) >> 3) & 0x70))

#define CP_ASYNC16(dst_u32, src_ptr) \
    asm volatile("cp.async.cg.shared.global [%0], [%1], 16;\n" \
                 :: "r"(dst_u32), "l"(src_ptr))
#define CP_COMMIT() asm volatile("cp.async.commit_group;\n" ::: "memory")
#define CP_WAIT0()  asm volatile("cp.async.wait_group 0;\n" ::: "memory")
#define CP_WAIT1()  asm volatile("cp.async.wait_group 1;\n" ::: "memory")

#define LDSM_X4(r0, r1, r2, r3, addr) \
    asm volatile("ldmatrix.sync.aligned.m8n8.x4.shared.b16 {%0,%1,%2,%3}, [%4];" \
                 : "=r"(r0), "=r"(r1), "=r"(r2), "=r"(r3) : "r"(addr))
#define MMA16816(d, a0, a1, a2, a3, b0, b1) \
    asm volatile("mma.sync.aligned.m16n8k16.row.col.f32.bf16.bf16.f32 " \
                 "{%0,%1,%2,%3},{%4,%5,%6,%7},{%8,%9},{%0,%1,%2,%3};" \
                 : "+f"((d)[0]), "+f"((d)[1]), "+f"((d)[2]), "+f"((d)[3]) \
                 : "r"(a0), "r"(a1), "r"(a2), "r"(a3), "r"(b0), "r"(b1))

// ---------------------------------------------------------------------------
// bf16x3 GEMM: C[M,N] = (Ahi+Alo)[M,K] @ (Bhi+Blo)[N,K]^T + bias
// CTA 128x128, KC=64, THREE-stage cp.async pipeline, ONE barrier per chunk.
// 8 warps in 2(M) x 4(N) grid, 64x32 warp tiles.
// Stage: Ahi 16KB | Alo 16KB | Bhi 16KB | Blo 16KB = 64KB; 3 stages = 192KB.
// ---------------------------------------------------------------------------
#define KC 64
#define STAGE_BYTES 65536
#define NSTAGE 3
#define GEMM_SMEM (1024 + NSTAGE * STAGE_BYTES)

__device__ __forceinline__ void load_chunk_tiles(
    const __nv_bfloat16* __restrict__ Ah, const __nv_bfloat16* __restrict__ Al,
    const __nv_bfloat16* __restrict__ Bh, const __nv_bfloat16* __restrict__ Bl,
    int K, int m0, int n0, int c, uint32_t st, int tid)
{
    #pragma unroll
    for (int t = 0; t < 4; t++) {
        int idx = t * 256 + tid;
        int row = idx >> 3;
        int col = idx & 7;
        uint32_t off = SWZ128(row * 128 + col * 16);
        size_t ga = (size_t)(m0 + row) * K + c * KC + col * 8;
        size_t gb = (size_t)(n0 + row) * K + c * KC + col * 8;
        CP_ASYNC16(st + off,         Ah + ga);
        CP_ASYNC16(st + 16384 + off, Al + ga);
        CP_ASYNC16(st + 32768 + off, Bh + gb);
        CP_ASYNC16(st + 49152 + off, Bl + gb);
    }
}

__global__ __launch_bounds__(256, 1)
void gemm_bf16x3_kernel(const __nv_bfloat16* __restrict__ Ah,
                        const __nv_bfloat16* __restrict__ Al,
                        const __nv_bfloat16* __restrict__ Bh,
                        const __nv_bfloat16* __restrict__ Bl,
                        const float* __restrict__ bias,
                        float* __restrict__ C,
                        int N, int K)
{
    extern __shared__ char smem[];
    const uint32_t sb = smem_u32(smem);
    const uint32_t tiles = (sb + 1023) & ~1023u;
    const int tid  = threadIdx.x;
    const int wid  = tid >> 5;
    const int lane = tid & 31;
    const int m0 = blockIdx.y * 128;
    const int n0 = blockIdx.x * 128;
    const int NCHUNK = K / KC;

    const int warpM = wid >> 2;        // 0..1
    const int warpN = wid & 3;         // 0..3

    float acc[4][4][4];
    #pragma unroll
    for (int mt = 0; mt < 4; mt++)
        #pragma unroll
        for (int nt = 0; nt < 4; nt++)
            #pragma unroll
            for (int e = 0; e < 4; e++) acc[mt][nt][e] = 0.0f;

    // A ldmatrix.x4 (m16 x k16)
    const int aRowBase  = warpM * 64 + (lane & 15);
    const int aByteSel  = (lane >> 4) * 16;
    // B ldmatrix.x4 (two n8 tiles x k16) — verified in R6
    const int bRowSel   = warpN * 32 + (lane & 7) + ((lane >> 4) & 1) * 8;
    const int bByteSel  = ((lane >> 3) & 1) * 16;

    load_chunk_tiles(Ah, Al, Bh, Bl, K, m0, n0, 0, tiles + 0 * STAGE_BYTES, tid);
    CP_COMMIT();
    load_chunk_tiles(Ah, Al, Bh, Bl, K, m0, n0, 1, tiles + 1 * STAGE_BYTES, tid);
    CP_COMMIT();

    for (int c = 0; c < NCHUNK; ++c) {
        if (c < NCHUNK - 1) { CP_WAIT1(); } else { CP_WAIT0(); }
        __syncthreads();   // chunk c resident; prior-iter reads of stage (c+2)%3 done

        if (c + 2 < NCHUNK) {
            load_chunk_tiles(Ah, Al, Bh, Bl, K, m0, n0, c + 2,
                             tiles + ((c + 2) % NSTAGE) * STAGE_BYTES, tid);
            CP_COMMIT();
        }

        const uint32_t st  = tiles + (c % NSTAGE) * STAGE_BYTES;
        const uint32_t aHi = st;
        const uint32_t aLo = st + 16384;
        const uint32_t bHi = st + 32768;
        const uint32_t bLo = st + 49152;

        #pragma unroll
        for (int kk = 0; kk < 4; kk++) {
            uint32_t bh[2][4], bl[2][4];
            #pragma unroll
            for (int p = 0; p < 2; p++) {
                uint32_t boff = SWZ128((uint32_t)((bRowSel + p * 16) * 128 + kk * 32 + bByteSel));
                LDSM_X4(bh[p][0], bh[p][1], bh[p][2], bh[p][3], bHi + boff);
                LDSM_X4(bl[p][0], bl[p][1], bl[p][2], bl[p][3], bLo + boff);
            }
            #pragma unroll
            for (int mt = 0; mt < 4; mt++) {
                uint32_t aoff = SWZ128((uint32_t)((aRowBase + mt * 16) * 128 + kk * 32 + aByteSel));
                uint32_t ah0, ah1, ah2, ah3, al0, al1, al2, al3;
                LDSM_X4(ah0, ah1, ah2, ah3, aHi + aoff);
                LDSM_X4(al0, al1, al2, al3, aLo + aoff);
                #pragma unroll
                for (int nt = 0; nt < 4; nt++) {
                    uint32_t b0 = bh[nt >> 1][(nt & 1) * 2];
                    uint32_t b1 = bh[nt >> 1][(nt & 1) * 2 + 1];
                    uint32_t c0 = bl[nt >> 1][(nt & 1) * 2];
                    uint32_t c1 = bl[nt >> 1][(nt & 1) * 2 + 1];
                    MMA16816(acc[mt][nt], ah0, ah1, ah2, ah3, b0, b1);
                    MMA16816(acc[mt][nt], al0, al1, al2, al3, b0, b1);
                    MMA16816(acc[mt][nt], ah0, ah1, ah2, ah3, c0, c1);
                }
            }
        }
    }

    // epilogue: bias + store
    #pragma unroll
    for (int mt = 0; mt < 4; mt++) {
        int r0 = m0 + warpM * 64 + mt * 16 + (lane >> 2);
        #pragma unroll
        for (int nt = 0; nt < 4; nt++) {
            int c0 = n0 + warpN * 32 + nt * 8 + (lane & 3) * 2;
            float2 bv = *(const float2*)(bias + c0);
            float2 o0 = make_float2(acc[mt][nt][0] + bv.x, acc[mt][nt][1] + bv.y);
            float2 o1 = make_float2(acc[mt][nt][2] + bv.x, acc[mt][nt][3] + bv.y);
            *(float2*)(C + (size_t)r0 * N + c0)       = o0;
            *(float2*)(C + (size_t)(r0 + 8) * N + c0) = o1;
        }
    }
}

// ---------------------------------------------------------------------------
// Split fp32 -> bf16 hi + bf16 residual lo
// ---------------------------------------------------------------------------
__global__ __launch_bounds__(256)
void conv_split_kernel(const float* __restrict__ in,
                       __nv_bfloat16* __restrict__ hi,
                       __nv_bfloat16* __restrict__ lo, int n4)
{
    int i = blockIdx.x * 256 + threadIdx.x;
    if (i >= n4) return;
    float4 v = ((const float4*)in)[i];
    __nv_bfloat16 h0 = __float2bfloat16(v.x);
    __nv_bfloat16 h1 = __float2bfloat16(v.y);
    __nv_bfloat16 h2 = __float2bfloat16(v.z);
    __nv_bfloat16 h3 = __float2bfloat16(v.w);
    __nv_bfloat16 l0 = __float2bfloat16(v.x - __bfloat162float(h0));
    __nv_bfloat16 l1 = __float2bfloat16(v.y - __bfloat162float(h1));
    __nv_bfloat16 l2 = __float2bfloat16(v.z - __bfloat162float(h2));
    __nv_bfloat16 l3 = __float2bfloat16(v.w - __bfloat162float(h3));
    ((__nv_bfloat162*)hi)[2 * i + 0] = __nv_bfloat162(h0, h1);
    ((__nv_bfloat162*)hi)[2 * i + 1] = __nv_bfloat162(h2, h3);
    ((__nv_bfloat162*)lo)[2 * i + 0] = __nv_bfloat162(l0, l1);
    ((__nv_bfloat162*)lo)[2 * i + 1] = __nv_bfloat162(l2, l3);
}

// ---------------------------------------------------------------------------
// Transpose + split: W[K,N] fp32 -> Wt hi/lo [N,K] bf16
// ---------------------------------------------------------------------------
__global__ __launch_bounds__(256)
void conv_transpose_kernel(const float* __restrict__ W,
                           __nv_bfloat16* __restrict__ hi,
                           __nv_bfloat16* __restrict__ lo, int K, int N)
{
    __shared__ float tile[32][33];
    const int n0 = blockIdx.x * 32;
    const int k0 = blockIdx.y * 32;
    const int tx = threadIdx.x & 31;
    const int ty = threadIdx.x >> 5;

    #pragma unroll
    for (int j = ty; j < 32; j += 8)
        tile[j][tx] = W[(size_t)(k0 + j) * N + n0 + tx];
    __syncthreads();

    #pragma unroll
    for (int j = ty; j < 32; j += 8) {
        float v = tile[tx][j];
        __nv_bfloat16 h = __float2bfloat16(v);
        __nv_bfloat16 l = __float2bfloat16(v - __bfloat162float(h));
        size_t o = (size_t)(n0 + j) * K + k0 + tx;
        hi[o] = h;
        lo[o] = l;
    }
}

// ---------------------------------------------------------------------------
// Fenwick sparse attention — parallel-position formulation.
// Lane j (j<12) owns position: j==0 -> t (diag), j>=1 -> t - 2^(j-1).
// Phase 1: 12 dot products computed concurrently (one per lane, float4, MLP).
// Phase 2: V accumulate with per-lane dims, weights broadcast via shfl.
// Fused bf16 hi/lo split output.
// ---------------------------------------------------------------------------
__global__ __launch_bounds__(256)
void fenwick_attn_kernel(const float* __restrict__ qkv,
                         __nv_bfloat16* __restrict__ outHi,
                         __nv_bfloat16* __restrict__ outLo)
{
    const int warp = threadIdx.x >> 5;
    const int lane = threadIdx.x & 31;
    const int t  = blockIdx.x * 8 + warp;
    const int bh = blockIdx.y;
    const int b = bh >> 4;
    const int h = bh & 15;

    const float scale = 0.125f;   // 64^-0.5
    const size_t rowStride = 3 * CH;
    const float* base = qkv + (size_t)b * SEQ * rowStride;

    // my position
    bool active;
    int myPos;
    if (lane == 0)       { myPos = t; active = true; }
    else                 { int step = 1 << (lane - 1);
                           myPos = t - step;
                           active = (lane < 12) && (myPos >= 0); }
    if (!active) myPos = t;   // safe address

    // Phase 1: per-lane dot product q[t] . K[myPos]
    float s = -CUDART_INF_F;
    if (active) {
        const float4* qp4 = (const float4*)(base + (size_t)t * rowStride + h * DH);
        const float4* kp4 = (const float4*)(base + (size_t)myPos * rowStride + CH + h * DH);
        float d = 0.0f;
        #pragma unroll
        for (int i = 0; i < 16; i++) {
            float4 qv = qp4[i];
            float4 kv = kp4[i];
            d += qv.x * kv.x + qv.y * kv.y + qv.z * kv.z + qv.w * kv.w;
        }
        s = d * scale;
    }

    // softmax over active lanes
    float m = s;
    #pragma unroll
    for (int off = 16; off; off >>= 1) m = fmaxf(m, __shfl_xor_sync(0xFFFFFFFFu, m, off));
    float e = active ? __expf(s - m) : 0.0f;
    float denom = e;
    #pragma unroll
    for (int off = 16; off; off >>= 1) denom += __shfl_xor_sync(0xFFFFFFFFu, denom, off);
    const float inv = 1.0f / denom;

    // Phase 2: out[dim] = sum_j e_j * V[pos_j][dim]; lane owns dims {lane, lane+32}
    float o0 = 0.0f, o1 = 0.0f;
    #pragma unroll
    for (int j = 0; j < 12; j++) {
        float ej = __shfl_sync(0xFFFFFFFFu, e, j);
        int   pj = __shfl_sync(0xFFFFFFFFu, myPos, j);
        const float* vp = base + (size_t)pj * rowStride + 2 * CH + h * DH;
        o0 = fmaf(ej, vp[lane], o0);         // ej == 0 for inactive lanes
        o1 = fmaf(ej, vp[lane + 32], o1);
    }
    o0 *= inv;
    o1 *= inv;

    const size_t o = ((size_t)b * SEQ + t) * CH + h * DH;
    __nv_bfloat16 h0 = __float2bfloat16(o0);
    __nv_bfloat16 h1 = __float2bfloat16(o1);
    outHi[o + lane]      = h0;
    outHi[o + lane + 32] = h1;
    outLo[o + lane]      = __float2bfloat16(o0 - __bfloat162float(h0));
    outLo[o + lane + 32] = __float2bfloat16(o1 - __bfloat162float(h1));
}

// ---------------------------------------------------------------------------
// Launch
// ---------------------------------------------------------------------------
extern "C" void kernel_launch(void* const* d_in, const int* in_sizes, int n_in,
                              void* d_out, int out_size)
{
    const float* x      = (const float*)d_in[0];
    const float* W_qkv  = (const float*)d_in[1];
    const float* b_qkv  = (const float*)d_in[2];
    const float* W_proj = (const float*)d_in[3];
    const float* b_proj = (const float*)d_in[4];
    float* out = (float*)d_out;

    float *qkv;
    __nv_bfloat16 *Ahi, *Alo, *BQhi, *BQlo, *BPhi, *BPlo;
    cudaGetSymbolAddress((void**)&qkv,  g_qkv);
    cudaGetSymbolAddress((void**)&Ahi,  g_Ahi);
    cudaGetSymbolAddress((void**)&Alo,  g_Alo);
    cudaGetSymbolAddress((void**)&BQhi, g_BQhi);
    cudaGetSymbolAddress((void**)&BQlo, g_BQlo);
    cudaGetSymbolAddress((void**)&BPhi, g_BPhi);
    cudaGetSymbolAddress((void**)&BPlo, g_BPlo);

    cudaFuncSetAttribute(gemm_bf16x3_kernel,
                         cudaFuncAttributeMaxDynamicSharedMemorySize, GEMM_SMEM);

    conv_transpose_kernel<<<dim3(3 * CH / 32, CH / 32), 256>>>(W_qkv, BQhi, BQlo, CH, 3 * CH);
    conv_transpose_kernel<<<dim3(CH / 32, CH / 32), 256>>>(W_proj, BPhi, BPlo, CH, CH);
    conv_split_kernel<<<(MROWS * CH / 4 + 255) / 256, 256>>>(x, Ahi, Alo, MROWS * CH / 4);

    // GEMM1: [4096, 3072] = x @ W_qkv + b_qkv
    gemm_bf16x3_kernel<<<dim3(3 * CH / 128, MROWS / 128), 256, GEMM_SMEM>>>(
        Ahi, Alo, BQhi, BQlo, b_qkv, qkv, 3 * CH, CH);

    // Attention with fused hi/lo split output (overwrites Ahi/Alo)
    fenwick_attn_kernel<<<dim3(SEQ / 8, BATCH * HEADS), 256>>>(qkv, Ahi, Alo);

    // GEMM2: [4096, 1024] = att @ W_proj + b_proj
    gemm_bf16x3_kernel<<<dim3(CH / 128, MROWS / 128), 256, GEMM_SMEM>>>(
        Ahi, Alo, BPhi, BPlo, b_proj, out, CH, CH);
}

// round 9
// speedup vs baseline: 1.5907x; 1.3320x over previous
#include <cuda_runtime.h>
#include <cuda_fp16.h>
#include <math_constants.h>
#include <cstdint>

// Problem constants
#define BATCH 2
#define SEQ   2048
#define CH    1024
#define HEADS 16
#define DH    64
#define MROWS (BATCH*SEQ)   // 4096

// ---------------------------------------------------------------------------
// Device scratch
// ---------------------------------------------------------------------------
__device__ float  g_qkv[(size_t)MROWS * 3 * CH];
__device__ __half g_Ahi[(size_t)MROWS * CH];
__device__ __half g_Alo[(size_t)MROWS * CH];
__device__ __half g_BQ[(size_t)(3*CH) * CH];   // W_qkv^T fp16
__device__ __half g_BP[(size_t)CH * CH];       // W_proj^T fp16

// ---------------------------------------------------------------------------
// Helpers
// ---------------------------------------------------------------------------
__device__ __forceinline__ uint32_t smem_u32(const void* p) {
    uint32_t a;
    asm("{ .reg .u64 t; cvta.to.shared.u64 t, %1; cvt.u32.u64 %0, t; }"
        : "=r"(a) : "l"(p));
    return a;
}

#define SWZ128(o) ((o) ^ (((o) >> 3) & 0x70))

#define CP_ASYNC16(dst_u32, src_ptr) \
    asm volatile("cp.async.cg.shared.global [%0], [%1], 16;\n" \
                 :: "r"(dst_u32), "l"(src_ptr))
#define CP_COMMIT() asm volatile("cp.async.commit_group;\n" ::: "memory")
#define CP_WAIT0()  asm volatile("cp.async.wait_group 0;\n" ::: "memory")
#define CP_WAIT1()  asm volatile("cp.async.wait_group 1;\n" ::: "memory")

#define LDSM_X4(r0, r1, r2, r3, addr) \
    asm volatile("ldmatrix.sync.aligned.m8n8.x4.shared.b16 {%0,%1,%2,%3}, [%4];" \
                 : "=r"(r0), "=r"(r1), "=r"(r2), "=r"(r3) : "r"(addr))
// fp16 MMA, f32 accumulate
#define MMA16816(d, a0, a1, a2, a3, b0, b1) \
    asm volatile("mma.sync.aligned.m16n8k16.row.col.f32.f16.f16.f32 " \
                 "{%0,%1,%2,%3},{%4,%5,%6,%7},{%8,%9},{%0,%1,%2,%3};" \
                 : "+f"((d)[0]), "+f"((d)[1]), "+f"((d)[2]), "+f"((d)[3]) \
                 : "r"(a0), "r"(a1), "r"(a2), "r"(a3), "r"(b0), "r"(b1))

// ---------------------------------------------------------------------------
// fp16x2 GEMM: C[M,N] = (Ahi+Alo)[M,K] @ B[N,K]^T + bias   (B single fp16)
// CTA 128x128, KC=64, 3-stage cp.async pipeline, one barrier per chunk.
// 8 warps 2(M)x4(N), 64x32 warp tiles. Register fragment double buffering.
// Stage: Ahi 16KB | Alo 16KB | B 16KB = 48KB; 3 stages.
// ---------------------------------------------------------------------------
#define KC 64
#define STAGE_BYTES 49152
#define NSTAGE 3
#define GEMM_SMEM (1024 + NSTAGE * STAGE_BYTES)

__device__ __forceinline__ void load_chunk_tiles(
    const __half* __restrict__ Ah, const __half* __restrict__ Al,
    const __half* __restrict__ Bs,
    int K, int m0, int n0, int c, uint32_t st, int tid)
{
    #pragma unroll
    for (int t = 0; t < 4; t++) {
        int idx = t * 256 + tid;     // 0..1023
        int row = idx >> 3;          // 0..127
        int col = idx & 7;           // 16B chunk
        uint32_t off = SWZ128(row * 128 + col * 16);
        size_t ga = (size_t)(m0 + row) * K + c * KC + col * 8;
        size_t gb = (size_t)(n0 + row) * K + c * KC + col * 8;
        CP_ASYNC16(st + off,         Ah + ga);
        CP_ASYNC16(st + 16384 + off, Al + ga);
        CP_ASYNC16(st + 32768 + off, Bs + gb);
    }
}

__global__ __launch_bounds__(256, 1)
void gemm_fp16x2_kernel(const __half* __restrict__ Ah,
                        const __half* __restrict__ Al,
                        const __half* __restrict__ Bs,
                        const float* __restrict__ bias,
                        float* __restrict__ C,
                        int N, int K)
{
    extern __shared__ char smem[];
    const uint32_t sb = smem_u32(smem);
    const uint32_t tiles = (sb + 1023) & ~1023u;
    const int tid  = threadIdx.x;
    const int wid  = tid >> 5;
    const int lane = tid & 31;
    const int m0 = blockIdx.y * 128;
    const int n0 = blockIdx.x * 128;
    const int NCHUNK = K / KC;

    const int warpM = wid >> 2;        // 0..1
    const int warpN = wid & 3;         // 0..3

    float acc[4][4][4];
    #pragma unroll
    for (int mt = 0; mt < 4; mt++)
        #pragma unroll
        for (int nt = 0; nt < 4; nt++)
            #pragma unroll
            for (int e = 0; e < 4; e++) acc[mt][nt][e] = 0.0f;

    // A ldmatrix.x4 (m16 x k16)
    const int aRowBase  = warpM * 64 + (lane & 15);
    const int aByteSel  = (lane >> 4) * 16;
    // B ldmatrix.x4 (two n8 tiles x k16) — layout verified R6/R7
    const int bRowSel   = warpN * 32 + (lane & 7) + ((lane >> 4) & 1) * 8;
    const int bByteSel  = ((lane >> 3) & 1) * 16;

    load_chunk_tiles(Ah, Al, Bs, K, m0, n0, 0, tiles + 0 * STAGE_BYTES, tid);
    CP_COMMIT();
    load_chunk_tiles(Ah, Al, Bs, K, m0, n0, 1, tiles + 1 * STAGE_BYTES, tid);
    CP_COMMIT();

    // register fragment double buffers
    uint32_t fah[2][4][4], fal[2][4][4], fb[2][2][4];

    #define LOAD_FRAGS(kk, buf, aHi, aLo, bB) do { \
        _Pragma("unroll") \
        for (int mt = 0; mt < 4; mt++) { \
            uint32_t aoff = SWZ128((uint32_t)((aRowBase + mt * 16) * 128 + (kk) * 32 + aByteSel)); \
            LDSM_X4(fah[buf][mt][0], fah[buf][mt][1], fah[buf][mt][2], fah[buf][mt][3], (aHi) + aoff); \
            LDSM_X4(fal[buf][mt][0], fal[buf][mt][1], fal[buf][mt][2], fal[buf][mt][3], (aLo) + aoff); \
        } \
        _Pragma("unroll") \
        for (int p = 0; p < 2; p++) { \
            uint32_t boff = SWZ128((uint32_t)((bRowSel + p * 16) * 128 + (kk) * 32 + bByteSel)); \
            LDSM_X4(fb[buf][p][0], fb[buf][p][1], fb[buf][p][2], fb[buf][p][3], (bB) + boff); \
        } \
    } while (0)

    for (int c = 0; c < NCHUNK; ++c) {
        if (c < NCHUNK - 1) { CP_WAIT1(); } else { CP_WAIT0(); }
        __syncthreads();   // chunk c resident; stage (c+2)%3 free

        if (c + 2 < NCHUNK) {
            load_chunk_tiles(Ah, Al, Bs, K, m0, n0, c + 2,
                             tiles + ((c + 2) % NSTAGE) * STAGE_BYTES, tid);
            CP_COMMIT();
        }

        const uint32_t st  = tiles + (c % NSTAGE) * STAGE_BYTES;
        const uint32_t aHi = st;
        const uint32_t aLo = st + 16384;
        const uint32_t bB  = st + 32768;

        LOAD_FRAGS(0, 0, aHi, aLo, bB);

        #pragma unroll
        for (int kk = 0; kk < 4; kk++) {
            const int cur = kk & 1;
            if (kk < 3) {
                const int nxt = cur ^ 1;
                switch (kk) {
                    case 0: LOAD_FRAGS(1, nxt, aHi, aLo, bB); break;
                    case 1: LOAD_FRAGS(2, nxt, aHi, aLo, bB); break;
                    case 2: LOAD_FRAGS(3, nxt, aHi, aLo, bB); break;
                }
            }
            // Pass 1: ahi x B
            #pragma unroll
            for (int mt = 0; mt < 4; mt++)
                #pragma unroll
                for (int nt = 0; nt < 4; nt++)
                    MMA16816(acc[mt][nt],
                             fah[cur][mt][0], fah[cur][mt][1], fah[cur][mt][2], fah[cur][mt][3],
                             fb[cur][nt >> 1][(nt & 1) * 2], fb[cur][nt >> 1][(nt & 1) * 2 + 1]);
            // Pass 2: alo x B
            #pragma unroll
            for (int mt = 0; mt < 4; mt++)
                #pragma unroll
                for (int nt = 0; nt < 4; nt++)
                    MMA16816(acc[mt][nt],
                             fal[cur][mt][0], fal[cur][mt][1], fal[cur][mt][2], fal[cur][mt][3],
                             fb[cur][nt >> 1][(nt & 1) * 2], fb[cur][nt >> 1][(nt & 1) * 2 + 1]);
        }
    }
    #undef LOAD_FRAGS

    // epilogue: bias + store
    #pragma unroll
    for (int mt = 0; mt < 4; mt++) {
        int r0 = m0 + warpM * 64 + mt * 16 + (lane >> 2);
        #pragma unroll
        for (int nt = 0; nt < 4; nt++) {
            int c0 = n0 + warpN * 32 + nt * 8 + (lane & 3) * 2;
            float2 bv = *(const float2*)(bias + c0);
            float2 o0 = make_float2(acc[mt][nt][0] + bv.x, acc[mt][nt][1] + bv.y);
            float2 o1 = make_float2(acc[mt][nt][2] + bv.x, acc[mt][nt][3] + bv.y);
            *(float2*)(C + (size_t)r0 * N + c0)       = o0;
            *(float2*)(C + (size_t)(r0 + 8) * N + c0) = o1;
        }
    }
}

// ---------------------------------------------------------------------------
// Split fp32 -> fp16 hi + fp16 residual lo
// ---------------------------------------------------------------------------
__global__ __launch_bounds__(256)
void conv_split_kernel(const float* __restrict__ in,
                       __half* __restrict__ hi,
                       __half* __restrict__ lo, int n4)
{
    int i = blockIdx.x * 256 + threadIdx.x;
    if (i >= n4) return;
    float4 v = ((const float4*)in)[i];
    __half h0 = __float2half_rn(v.x);
    __half h1 = __float2half_rn(v.y);
    __half h2 = __float2half_rn(v.z);
    __half h3 = __float2half_rn(v.w);
    __half l0 = __float2half_rn(v.x - __half2float(h0));
    __half l1 = __float2half_rn(v.y - __half2float(h1));
    __half l2 = __float2half_rn(v.z - __half2float(h2));
    __half l3 = __float2half_rn(v.w - __half2float(h3));
    ((__half2*)hi)[2 * i + 0] = __halves2half2(h0, h1);
    ((__half2*)hi)[2 * i + 1] = __halves2half2(h2, h3);
    ((__half2*)lo)[2 * i + 0] = __halves2half2(l0, l1);
    ((__half2*)lo)[2 * i + 1] = __halves2half2(l2, l3);
}

// ---------------------------------------------------------------------------
// Transpose: W[K,N] fp32 -> Wt[N,K] fp16 (single precision level)
// ---------------------------------------------------------------------------
__global__ __launch_bounds__(256)
void conv_transpose_kernel(const float* __restrict__ W,
                           __half* __restrict__ o, int K, int N)
{
    __shared__ float tile[32][33];
    const int n0 = blockIdx.x * 32;
    const int k0 = blockIdx.y * 32;
    const int tx = threadIdx.x & 31;
    const int ty = threadIdx.x >> 5;

    #pragma unroll
    for (int j = ty; j < 32; j += 8)
        tile[j][tx] = W[(size_t)(k0 + j) * N + n0 + tx];
    __syncthreads();

    #pragma unroll
    for (int j = ty; j < 32; j += 8)
        o[(size_t)(n0 + j) * K + k0 + tx] = __float2half_rn(tile[tx][j]);
}

// ---------------------------------------------------------------------------
// Fenwick sparse attention — parallel-position formulation (R8, verified).
// Fused fp16 hi/lo split output.
// ---------------------------------------------------------------------------
__global__ __launch_bounds__(256)
void fenwick_attn_kernel(const float* __restrict__ qkv,
                         __half* __restrict__ outHi,
                         __half* __restrict__ outLo)
{
    const int warp = threadIdx.x >> 5;
    const int lane = threadIdx.x & 31;
    const int t  = blockIdx.x * 8 + warp;
    const int bh = blockIdx.y;
    const int b = bh >> 4;
    const int h = bh & 15;

    const float scale = 0.125f;
    const size_t rowStride = 3 * CH;
    const float* base = qkv + (size_t)b * SEQ * rowStride;

    bool active;
    int myPos;
    if (lane == 0) { myPos = t; active = true; }
    else           { int step = 1 << (lane - 1);
                     myPos = t - step;
                     active = (lane < 12) && (myPos >= 0); }
    if (!active) myPos = t;

    float s = -CUDART_INF_F;
    if (active) {
        const float4* qp4 = (const float4*)(base + (size_t)t * rowStride + h * DH);
        const float4* kp4 = (const float4*)(base + (size_t)myPos * rowStride + CH + h * DH);
        float d = 0.0f;
        #pragma unroll
        for (int i = 0; i < 16; i++) {
            float4 qv = qp4[i];
            float4 kv = kp4[i];
            d += qv.x * kv.x + qv.y * kv.y + qv.z * kv.z + qv.w * kv.w;
        }
        s = d * scale;
    }

    float m = s;
    #pragma unroll
    for (int off = 16; off; off >>= 1) m = fmaxf(m, __shfl_xor_sync(0xFFFFFFFFu, m, off));
    float e = active ? __expf(s - m) : 0.0f;
    float denom = e;
    #pragma unroll
    for (int off = 16; off; off >>= 1) denom += __shfl_xor_sync(0xFFFFFFFFu, denom, off);
    const float inv = 1.0f / denom;

    float o0 = 0.0f, o1 = 0.0f;
    #pragma unroll
    for (int j = 0; j < 12; j++) {
        float ej = __shfl_sync(0xFFFFFFFFu, e, j);
        int   pj = __shfl_sync(0xFFFFFFFFu, myPos, j);
        const float* vp = base + (size_t)pj * rowStride + 2 * CH + h * DH;
        o0 = fmaf(ej, vp[lane], o0);
        o1 = fmaf(ej, vp[lane + 32], o1);
    }
    o0 *= inv;
    o1 *= inv;

    const size_t o = ((size_t)b * SEQ + t) * CH + h * DH;
    __half h0 = __float2half_rn(o0);
    __half h1 = __float2half_rn(o1);
    outHi[o + lane]      = h0;
    outHi[o + lane + 32] = h1;
    outLo[o + lane]      = __float2half_rn(o0 - __half2float(h0));
    outLo[o + lane + 32] = __float2half_rn(o1 - __half2float(h1));
}

// ---------------------------------------------------------------------------
// Launch
// ---------------------------------------------------------------------------
extern "C" void kernel_launch(void* const* d_in, const int* in_sizes, int n_in,
                              void* d_out, int out_size)
{
    const float* x      = (const float*)d_in[0];
    const float* W_qkv  = (const float*)d_in[1];
    const float* b_qkv  = (const float*)d_in[2];
    const float* W_proj = (const float*)d_in[3];
    const float* b_proj = (const float*)d_in[4];
    float* out = (float*)d_out;

    float *qkv;
    __half *Ahi, *Alo, *BQ, *BP;
    cudaGetSymbolAddress((void**)&qkv, g_qkv);
    cudaGetSymbolAddress((void**)&Ahi, g_Ahi);
    cudaGetSymbolAddress((void**)&Alo, g_Alo);
    cudaGetSymbolAddress((void**)&BQ,  g_BQ);
    cudaGetSymbolAddress((void**)&BP,  g_BP);

    cudaFuncSetAttribute(gemm_fp16x2_kernel,
                         cudaFuncAttributeMaxDynamicSharedMemorySize, GEMM_SMEM);

    conv_transpose_kernel<<<dim3(3 * CH / 32, CH / 32), 256>>>(W_qkv, BQ, CH, 3 * CH);
    conv_transpose_kernel<<<dim3(CH / 32, CH / 32), 256>>>(W_proj, BP, CH, CH);
    conv_split_kernel<<<(MROWS * CH / 4 + 255) / 256, 256>>>(x, Ahi, Alo, MROWS * CH / 4);

    // GEMM1: [4096, 3072] = x @ W_qkv + b_qkv
    gemm_fp16x2_kernel<<<dim3(3 * CH / 128, MROWS / 128), 256, GEMM_SMEM>>>(
        Ahi, Alo, BQ, b_qkv, qkv, 3 * CH, CH);

    // Attention with fused fp16 hi/lo split output (overwrites Ahi/Alo)
    fenwick_attn_kernel<<<dim3(SEQ / 8, BATCH * HEADS), 256>>>(qkv, Ahi, Alo);

    // GEMM2: [4096, 1024] = att @ W_proj + b_proj
    gemm_fp16x2_kernel<<<dim3(CH / 128, MROWS / 128), 256, GEMM_SMEM>>>(
        Ahi, Alo, BP, b_proj, out, CH, CH);
}

// round 10
// speedup vs baseline: 2.1612x; 1.3586x over previous
#include <cuda_runtime.h>
#include <cuda_fp16.h>
#include <math_constants.h>
#include <cstdint>

// Problem constants
#define BATCH 2
#define SEQ   2048
#define CH    1024
#define HEADS 16
#define DH    64
#define MROWS (BATCH*SEQ)   // 4096

// ---------------------------------------------------------------------------
// Device scratch
// ---------------------------------------------------------------------------
__device__ float  g_qkv[(size_t)MROWS * 3 * CH];
__device__ __half g_A[(size_t)MROWS * CH];
__device__ __half g_BQ[(size_t)(3*CH) * CH];   // W_qkv^T fp16
__device__ __half g_BP[(size_t)CH * CH];       // W_proj^T fp16

// ---------------------------------------------------------------------------
// Helpers
// ---------------------------------------------------------------------------
__device__ __forceinline__ uint32_t smem_u32(const void* p) {
    uint32_t a;
    asm("{ .reg .u64 t; cvta.to.shared.u64 t, %1; cvt.u32.u64 %0, t; }"
        : "=r"(a) : "l"(p));
    return a;
}

#define SWZ128(o) ((o) ^ (((o) >> 3) & 0x70))

#define CP_ASYNC16(dst_u32, src_ptr) \
    asm volatile("cp.async.cg.shared.global [%0], [%1], 16;\n" \
                 :: "r"(dst_u32), "l"(src_ptr))
#define CP_COMMIT() asm volatile("cp.async.commit_group;\n" ::: "memory")
#define CP_WAIT0()  asm volatile("cp.async.wait_group 0;\n" ::: "memory")
#define CP_WAIT1()  asm volatile("cp.async.wait_group 1;\n" ::: "memory")
#define CP_WAIT2()  asm volatile("cp.async.wait_group 2;\n" ::: "memory")

#define LDSM_X4(r0, r1, r2, r3, addr) \
    asm volatile("ldmatrix.sync.aligned.m8n8.x4.shared.b16 {%0,%1,%2,%3}, [%4];" \
                 : "=r"(r0), "=r"(r1), "=r"(r2), "=r"(r3) : "r"(addr))
// fp16 MMA, f32 accumulate
#define MMA16816(d, a0, a1, a2, a3, b0, b1) \
    asm volatile("mma.sync.aligned.m16n8k16.row.col.f32.f16.f16.f32 " \
                 "{%0,%1,%2,%3},{%4,%5,%6,%7},{%8,%9},{%0,%1,%2,%3};" \
                 : "+f"((d)[0]), "+f"((d)[1]), "+f"((d)[2]), "+f"((d)[3]) \
                 : "r"(a0), "r"(a1), "r"(a2), "r"(a3), "r"(b0), "r"(b1))

// ---------------------------------------------------------------------------
// fp16 GEMM: C[M,N] = A[M,K] @ B[N,K]^T + bias
// CTA 128x128, KC=64, FOUR-stage cp.async pipeline (prefetch distance 3).
// 8 warps 2(M)x4(N), 64x32 warp tiles. Register fragment double buffering.
// Stage: A 16KB | B 16KB = 32KB; 4 stages = 128KB.
// ---------------------------------------------------------------------------
#define KC 64
#define STAGE_BYTES 32768
#define NSTAGE 4
#define GEMM_SMEM (1024 + NSTAGE * STAGE_BYTES)

__device__ __forceinline__ void load_chunk_tiles(
    const __half* __restrict__ A, const __half* __restrict__ B,
    int K, int m0, int n0, int c, uint32_t st, int tid)
{
    #pragma unroll
    for (int t = 0; t < 4; t++) {
        int idx = t * 256 + tid;     // 0..1023
        int row = idx >> 3;          // 0..127
        int col = idx & 7;           // 16B chunk
        uint32_t off = SWZ128(row * 128 + col * 16);
        size_t ga = (size_t)(m0 + row) * K + c * KC + col * 8;
        size_t gb = (size_t)(n0 + row) * K + c * KC + col * 8;
        CP_ASYNC16(st + off,         A + ga);
        CP_ASYNC16(st + 16384 + off, B + gb);
    }
}

__global__ __launch_bounds__(256, 1)
void gemm_fp16_kernel(const __half* __restrict__ A,
                      const __half* __restrict__ B,
                      const float* __restrict__ bias,
                      float* __restrict__ C,
                      int N, int K)
{
    extern __shared__ char smem[];
    const uint32_t sb = smem_u32(smem);
    const uint32_t tiles = (sb + 1023) & ~1023u;
    const int tid  = threadIdx.x;
    const int wid  = tid >> 5;
    const int lane = tid & 31;
    const int m0 = blockIdx.y * 128;
    const int n0 = blockIdx.x * 128;
    const int NCHUNK = K / KC;

    const int warpM = wid >> 2;        // 0..1
    const int warpN = wid & 3;         // 0..3

    float acc[4][4][4];
    #pragma unroll
    for (int mt = 0; mt < 4; mt++)
        #pragma unroll
        for (int nt = 0; nt < 4; nt++)
            #pragma unroll
            for (int e = 0; e < 4; e++) acc[mt][nt][e] = 0.0f;

    // A ldmatrix.x4 (m16 x k16)
    const int aRowBase  = warpM * 64 + (lane & 15);
    const int aByteSel  = (lane >> 4) * 16;
    // B ldmatrix.x4 (two n8 tiles x k16) — layout verified R6-R9
    const int bRowSel   = warpN * 32 + (lane & 7) + ((lane >> 4) & 1) * 8;
    const int bByteSel  = ((lane >> 3) & 1) * 16;

    // Prologue: 3 chunks in flight
    load_chunk_tiles(A, B, K, m0, n0, 0, tiles + 0 * STAGE_BYTES, tid);
    CP_COMMIT();
    if (NCHUNK > 1) {
        load_chunk_tiles(A, B, K, m0, n0, 1, tiles + 1 * STAGE_BYTES, tid);
        CP_COMMIT();
    }
    if (NCHUNK > 2) {
        load_chunk_tiles(A, B, K, m0, n0, 2, tiles + 2 * STAGE_BYTES, tid);
        CP_COMMIT();
    }

    // register fragment double buffers
    uint32_t fa[2][4][4], fb[2][2][4];

    #define LOAD_FRAGS(kk, buf, aB, bB) do { \
        _Pragma("unroll") \
        for (int mt = 0; mt < 4; mt++) { \
            uint32_t aoff = SWZ128((uint32_t)((aRowBase + mt * 16) * 128 + (kk) * 32 + aByteSel)); \
            LDSM_X4(fa[buf][mt][0], fa[buf][mt][1], fa[buf][mt][2], fa[buf][mt][3], (aB) + aoff); \
        } \
        _Pragma("unroll") \
        for (int p = 0; p < 2; p++) { \
            uint32_t boff = SWZ128((uint32_t)((bRowSel + p * 16) * 128 + (kk) * 32 + bByteSel)); \
            LDSM_X4(fb[buf][p][0], fb[buf][p][1], fb[buf][p][2], fb[buf][p][3], (bB) + boff); \
        } \
    } while (0)

    for (int c = 0; c < NCHUNK; ++c) {
        // ensure chunk c resident (leave later prefetches in flight)
        int remaining = NCHUNK - 1 - c;   // loads not yet required
        if (remaining >= 2)      { CP_WAIT2(); }
        else if (remaining == 1) { CP_WAIT1(); }
        else                     { CP_WAIT0(); }
        __syncthreads();   // all warps done reading the stage we're about to overwrite

        if (c + 3 < NCHUNK) {
            load_chunk_tiles(A, B, K, m0, n0, c + 3,
                             tiles + ((c + 3) % NSTAGE) * STAGE_BYTES, tid);
            CP_COMMIT();
        }

        const uint32_t st = tiles + (c % NSTAGE) * STAGE_BYTES;
        const uint32_t aB = st;
        const uint32_t bB = st + 16384;

        LOAD_FRAGS(0, 0, aB, bB);

        #pragma unroll
        for (int kk = 0; kk < 4; kk++) {
            const int cur = kk & 1;
            if (kk < 3) {
                const int nxt = cur ^ 1;
                switch (kk) {
                    case 0: LOAD_FRAGS(1, nxt, aB, bB); break;
                    case 1: LOAD_FRAGS(2, nxt, aB, bB); break;
                    case 2: LOAD_FRAGS(3, nxt, aB, bB); break;
                }
            }
            #pragma unroll
            for (int mt = 0; mt < 4; mt++)
                #pragma unroll
                for (int nt = 0; nt < 4; nt++)
                    MMA16816(acc[mt][nt],
                             fa[cur][mt][0], fa[cur][mt][1], fa[cur][mt][2], fa[cur][mt][3],
                             fb[cur][nt >> 1][(nt & 1) * 2], fb[cur][nt >> 1][(nt & 1) * 2 + 1]);
        }
    }
    #undef LOAD_FRAGS

    // epilogue: bias + store
    #pragma unroll
    for (int mt = 0; mt < 4; mt++) {
        int r0 = m0 + warpM * 64 + mt * 16 + (lane >> 2);
        #pragma unroll
        for (int nt = 0; nt < 4; nt++) {
            int c0 = n0 + warpN * 32 + nt * 8 + (lane & 3) * 2;
            float2 bv = *(const float2*)(bias + c0);
            float2 o0 = make_float2(acc[mt][nt][0] + bv.x, acc[mt][nt][1] + bv.y);
            float2 o1 = make_float2(acc[mt][nt][2] + bv.x, acc[mt][nt][3] + bv.y);
            *(float2*)(C + (size_t)r0 * N + c0)       = o0;
            *(float2*)(C + (size_t)(r0 + 8) * N + c0) = o1;
        }
    }
}

// ---------------------------------------------------------------------------
// Convert fp32 -> fp16
// ---------------------------------------------------------------------------
__global__ __launch_bounds__(256)
void conv_fp16_kernel(const float* __restrict__ in,
                      __half* __restrict__ o, int n4)
{
    int i = blockIdx.x * 256 + threadIdx.x;
    if (i >= n4) return;
    float4 v = ((const float4*)in)[i];
    ((__half2*)o)[2 * i + 0] = __halves2half2(__float2half_rn(v.x), __float2half_rn(v.y));
    ((__half2*)o)[2 * i + 1] = __halves2half2(__float2half_rn(v.z), __float2half_rn(v.w));
}

// ---------------------------------------------------------------------------
// Transpose: W[K,N] fp32 -> Wt[N,K] fp16
// ---------------------------------------------------------------------------
__global__ __launch_bounds__(256)
void conv_transpose_kernel(const float* __restrict__ W,
                           __half* __restrict__ o, int K, int N)
{
    __shared__ float tile[32][33];
    const int n0 = blockIdx.x * 32;
    const int k0 = blockIdx.y * 32;
    const int tx = threadIdx.x & 31;
    const int ty = threadIdx.x >> 5;

    #pragma unroll
    for (int j = ty; j < 32; j += 8)
        tile[j][tx] = W[(size_t)(k0 + j) * N + n0 + tx];
    __syncthreads();

    #pragma unroll
    for (int j = ty; j < 32; j += 8)
        o[(size_t)(n0 + j) * K + k0 + tx] = __float2half_rn(tile[tx][j]);
}

// ---------------------------------------------------------------------------
// Fenwick sparse attention — parallel-position formulation (verified R8/R9).
// fp16 output (feeds GEMM2 A operand directly).
// ---------------------------------------------------------------------------
__global__ __launch_bounds__(256)
void fenwick_attn_kernel(const float* __restrict__ qkv,
                         __half* __restrict__ outA)
{
    const int warp = threadIdx.x >> 5;
    const int lane = threadIdx.x & 31;
    const int t  = blockIdx.x * 8 + warp;
    const int bh = blockIdx.y;
    const int b = bh >> 4;
    const int h = bh & 15;

    const float scale = 0.125f;
    const size_t rowStride = 3 * CH;
    const float* base = qkv + (size_t)b * SEQ * rowStride;

    bool active;
    int myPos;
    if (lane == 0) { myPos = t; active = true; }
    else           { int step = 1 << (lane - 1);
                     myPos = t - step;
                     active = (lane < 12) && (myPos >= 0); }
    if (!active) myPos = t;

    float s = -CUDART_INF_F;
    if (active) {
        const float4* qp4 = (const float4*)(base + (size_t)t * rowStride + h * DH);
        const float4* kp4 = (const float4*)(base + (size_t)myPos * rowStride + CH + h * DH);
        float d = 0.0f;
        #pragma unroll
        for (int i = 0; i < 16; i++) {
            float4 qv = qp4[i];
            float4 kv = kp4[i];
            d += qv.x * kv.x + qv.y * kv.y + qv.z * kv.z + qv.w * kv.w;
        }
        s = d * scale;
    }

    float m = s;
    #pragma unroll
    for (int off = 16; off; off >>= 1) m = fmaxf(m, __shfl_xor_sync(0xFFFFFFFFu, m, off));
    float e = active ? __expf(s - m) : 0.0f;
    float denom = e;
    #pragma unroll
    for (int off = 16; off; off >>= 1) denom += __shfl_xor_sync(0xFFFFFFFFu, denom, off);
    const float inv = 1.0f / denom;

    float o0 = 0.0f, o1 = 0.0f;
    #pragma unroll
    for (int j = 0; j < 12; j++) {
        float ej = __shfl_sync(0xFFFFFFFFu, e, j);
        int   pj = __shfl_sync(0xFFFFFFFFu, myPos, j);
        const float* vp = base + (size_t)pj * rowStride + 2 * CH + h * DH;
        o0 = fmaf(ej, vp[lane], o0);
        o1 = fmaf(ej, vp[lane + 32], o1);
    }
    o0 *= inv;
    o1 *= inv;

    const size_t o = ((size_t)b * SEQ + t) * CH + h * DH;
    outA[o + lane]      = __float2half_rn(o0);
    outA[o + lane + 32] = __float2half_rn(o1);
}

// ---------------------------------------------------------------------------
// Launch
// ---------------------------------------------------------------------------
extern "C" void kernel_launch(void* const* d_in, const int* in_sizes, int n_in,
                              void* d_out, int out_size)
{
    const float* x      = (const float*)d_in[0];
    const float* W_qkv  = (const float*)d_in[1];
    const float* b_qkv  = (const float*)d_in[2];
    const float* W_proj = (const float*)d_in[3];
    const float* b_proj = (const float*)d_in[4];
    float* out = (float*)d_out;

    float *qkv;
    __half *A, *BQ, *BP;
    cudaGetSymbolAddress((void**)&qkv, g_qkv);
    cudaGetSymbolAddress((void**)&A,   g_A);
    cudaGetSymbolAddress((void**)&BQ,  g_BQ);
    cudaGetSymbolAddress((void**)&BP,  g_BP);

    cudaFuncSetAttribute(gemm_fp16_kernel,
                         cudaFuncAttributeMaxDynamicSharedMemorySize, GEMM_SMEM);

    conv_transpose_kernel<<<dim3(3 * CH / 32, CH / 32), 256>>>(W_qkv, BQ, CH, 3 * CH);
    conv_transpose_kernel<<<dim3(CH / 32, CH / 32), 256>>>(W_proj, BP, CH, CH);
    conv_fp16_kernel<<<(MROWS * CH / 4 + 255) / 256, 256>>>(x, A, MROWS * CH / 4);

    // GEMM1: [4096, 3072] = x @ W_qkv + b_qkv
    gemm_fp16_kernel<<<dim3(3 * CH / 128, MROWS / 128), 256, GEMM_SMEM>>>(
        A, BQ, b_qkv, qkv, 3 * CH, CH);

    // Attention, fp16 output (overwrites A)
    fenwick_attn_kernel<<<dim3(SEQ / 8, BATCH * HEADS), 256>>>(qkv, A);

    // GEMM2: [4096, 1024] = att @ W_proj + b_proj
    gemm_fp16_kernel<<<dim3(CH / 128, MROWS / 128), 256, GEMM_SMEM>>>(
        A, BP, b_proj, out, CH, CH);
}

// round 11
// speedup vs baseline: 2.3576x; 1.0909x over previous
#include <cuda_runtime.h>
#include <cuda_fp16.h>
#include <math_constants.h>
#include <cstdint>

// Problem constants
#define BATCH 2
#define SEQ   2048
#define CH    1024
#define HEADS 16
#define DH    64
#define MROWS (BATCH*SEQ)   // 4096

// ---------------------------------------------------------------------------
// Device scratch
// ---------------------------------------------------------------------------
__device__ float  g_qkv[(size_t)MROWS * 3 * CH];
__device__ __half g_A[(size_t)MROWS * CH];
__device__ __half g_BQ[(size_t)(3*CH) * CH];   // W_qkv^T fp16
__device__ __half g_BP[(size_t)CH * CH];       // W_proj^T fp16

// ---------------------------------------------------------------------------
// Helpers
// ---------------------------------------------------------------------------
__device__ __forceinline__ uint32_t smem_u32(const void* p) {
    uint32_t a;
    asm("{ .reg .u64 t; cvta.to.shared.u64 t, %1; cvt.u32.u64 %0, t; }"
        : "=r"(a) : "l"(p));
    return a;
}

#define SWZ128(o) ((o) ^ (((o) >> 3) & 0x70))

#define CP_ASYNC16(dst_u32, src_ptr) \
    asm volatile("cp.async.cg.shared.global [%0], [%1], 16;\n" \
                 :: "r"(dst_u32), "l"(src_ptr))
#define CP_COMMIT() asm volatile("cp.async.commit_group;\n" ::: "memory")
#define CP_WAIT0()  asm volatile("cp.async.wait_group 0;\n" ::: "memory")
#define CP_WAIT1()  asm volatile("cp.async.wait_group 1;\n" ::: "memory")

#define LDSM_X4(r0, r1, r2, r3, addr) \
    asm volatile("ldmatrix.sync.aligned.m8n8.x4.shared.b16 {%0,%1,%2,%3}, [%4];" \
                 : "=r"(r0), "=r"(r1), "=r"(r2), "=r"(r3) : "r"(addr))
// fp16 MMA, f32 accumulate
#define MMA16816(d, a0, a1, a2, a3, b0, b1) \
    asm volatile("mma.sync.aligned.m16n8k16.row.col.f32.f16.f16.f32 " \
                 "{%0,%1,%2,%3},{%4,%5,%6,%7},{%8,%9},{%0,%1,%2,%3};" \
                 : "+f"((d)[0]), "+f"((d)[1]), "+f"((d)[2]), "+f"((d)[3]) \
                 : "r"(a0), "r"(a1), "r"(a2), "r"(a3), "r"(b0), "r"(b1))

// ---------------------------------------------------------------------------
// fp16 GEMM: C[M,N] = A[M,K] @ B[N,K]^T + bias
// CTA 128x128, KC=64, 2-stage double buffer, TWO CTAs PER SM (occupancy play).
// 8 warps 2(M)x4(N), 64x32 warp tiles. Single-buffered register fragments.
// Stage: A 16KB | B 16KB = 32KB; 2 stages = 64KB/CTA -> 2 CTAs = 133KB/SM.
// __launch_bounds__(256, 2) caps regs at 128 (est. usage ~113, no spill).
// ---------------------------------------------------------------------------
#define KC 64
#define STAGE_BYTES 32768
#define GEMM_SMEM (1024 + 2 * STAGE_BYTES)   // 66560 B

__device__ __forceinline__ void load_chunk_tiles(
    const __half* __restrict__ A, const __half* __restrict__ B,
    int K, int m0, int n0, int c, uint32_t st, int tid)
{
    #pragma unroll
    for (int t = 0; t < 4; t++) {
        int idx = t * 256 + tid;     // 0..1023
        int row = idx >> 3;          // 0..127
        int col = idx & 7;           // 16B chunk
        uint32_t off = SWZ128(row * 128 + col * 16);
        size_t ga = (size_t)(m0 + row) * K + c * KC + col * 8;
        size_t gb = (size_t)(n0 + row) * K + c * KC + col * 8;
        CP_ASYNC16(st + off,         A + ga);
        CP_ASYNC16(st + 16384 + off, B + gb);
    }
}

__global__ __launch_bounds__(256, 2)
void gemm_fp16_kernel(const __half* __restrict__ A,
                      const __half* __restrict__ B,
                      const float* __restrict__ bias,
                      float* __restrict__ C,
                      int N, int K)
{
    extern __shared__ char smem[];
    const uint32_t sb = smem_u32(smem);
    const uint32_t tiles = (sb + 1023) & ~1023u;
    const int tid  = threadIdx.x;
    const int wid  = tid >> 5;
    const int lane = tid & 31;
    const int m0 = blockIdx.y * 128;
    const int n0 = blockIdx.x * 128;
    const int NCHUNK = K / KC;

    const int warpM = wid >> 2;        // 0..1
    const int warpN = wid & 3;         // 0..3

    float acc[4][4][4];
    #pragma unroll
    for (int mt = 0; mt < 4; mt++)
        #pragma unroll
        for (int nt = 0; nt < 4; nt++)
            #pragma unroll
            for (int e = 0; e < 4; e++) acc[mt][nt][e] = 0.0f;

    // A ldmatrix.x4 (m16 x k16)
    const int aRowBase  = warpM * 64 + (lane & 15);
    const int aByteSel  = (lane >> 4) * 16;
    // B ldmatrix.x4 (two n8 tiles x k16) — layout verified R6-R10
    const int bRowSel   = warpN * 32 + (lane & 7) + ((lane >> 4) & 1) * 8;
    const int bByteSel  = ((lane >> 3) & 1) * 16;

    load_chunk_tiles(A, B, K, m0, n0, 0, tiles, tid);
    CP_COMMIT();

    for (int c = 0; c < NCHUNK; ++c) {
        if (c + 1 < NCHUNK) {
            load_chunk_tiles(A, B, K, m0, n0, c + 1,
                             tiles + ((c + 1) & 1) * STAGE_BYTES, tid);
            CP_COMMIT();
            CP_WAIT1();
        } else {
            CP_WAIT0();
        }
        __syncthreads();

        const uint32_t st = tiles + (c & 1) * STAGE_BYTES;
        const uint32_t aB = st;
        const uint32_t bB = st + 16384;

        #pragma unroll
        for (int kk = 0; kk < 4; kk++) {
            uint32_t fa[4][4], fb[2][4];
            #pragma unroll
            for (int mt = 0; mt < 4; mt++) {
                uint32_t aoff = SWZ128((uint32_t)((aRowBase + mt * 16) * 128 + kk * 32 + aByteSel));
                LDSM_X4(fa[mt][0], fa[mt][1], fa[mt][2], fa[mt][3], aB + aoff);
            }
            #pragma unroll
            for (int p = 0; p < 2; p++) {
                uint32_t boff = SWZ128((uint32_t)((bRowSel + p * 16) * 128 + kk * 32 + bByteSel));
                LDSM_X4(fb[p][0], fb[p][1], fb[p][2], fb[p][3], bB + boff);
            }
            #pragma unroll
            for (int mt = 0; mt < 4; mt++)
                #pragma unroll
                for (int nt = 0; nt < 4; nt++)
                    MMA16816(acc[mt][nt],
                             fa[mt][0], fa[mt][1], fa[mt][2], fa[mt][3],
                             fb[nt >> 1][(nt & 1) * 2], fb[nt >> 1][(nt & 1) * 2 + 1]);
        }
        __syncthreads();
    }

    // epilogue: bias + store
    #pragma unroll
    for (int mt = 0; mt < 4; mt++) {
        int r0 = m0 + warpM * 64 + mt * 16 + (lane >> 2);
        #pragma unroll
        for (int nt = 0; nt < 4; nt++) {
            int c0 = n0 + warpN * 32 + nt * 8 + (lane & 3) * 2;
            float2 bv = *(const float2*)(bias + c0);
            float2 o0 = make_float2(acc[mt][nt][0] + bv.x, acc[mt][nt][1] + bv.y);
            float2 o1 = make_float2(acc[mt][nt][2] + bv.x, acc[mt][nt][3] + bv.y);
            *(float2*)(C + (size_t)r0 * N + c0)       = o0;
            *(float2*)(C + (size_t)(r0 + 8) * N + c0) = o1;
        }
    }
}

// ---------------------------------------------------------------------------
// Convert fp32 -> fp16
// ---------------------------------------------------------------------------
__global__ __launch_bounds__(256)
void conv_fp16_kernel(const float* __restrict__ in,
                      __half* __restrict__ o, int n4)
{
    int i = blockIdx.x * 256 + threadIdx.x;
    if (i >= n4) return;
    float4 v = ((const float4*)in)[i];
    ((__half2*)o)[2 * i + 0] = __halves2half2(__float2half_rn(v.x), __float2half_rn(v.y));
    ((__half2*)o)[2 * i + 1] = __halves2half2(__float2half_rn(v.z), __float2half_rn(v.w));
}

// ---------------------------------------------------------------------------
// Transpose: W[K,N] fp32 -> Wt[N,K] fp16
// ---------------------------------------------------------------------------
__global__ __launch_bounds__(256)
void conv_transpose_kernel(const float* __restrict__ W,
                           __half* __restrict__ o, int K, int N)
{
    __shared__ float tile[32][33];
    const int n0 = blockIdx.x * 32;
    const int k0 = blockIdx.y * 32;
    const int tx = threadIdx.x & 31;
    const int ty = threadIdx.x >> 5;

    #pragma unroll
    for (int j = ty; j < 32; j += 8)
        tile[j][tx] = W[(size_t)(k0 + j) * N + n0 + tx];
    __syncthreads();

    #pragma unroll
    for (int j = ty; j < 32; j += 8)
        o[(size_t)(n0 + j) * K + k0 + tx] = __float2half_rn(tile[tx][j]);
}

// ---------------------------------------------------------------------------
// Fenwick sparse attention — parallel-position formulation (verified R8-R10).
// fp16 output (feeds GEMM2 A operand directly).
// ---------------------------------------------------------------------------
__global__ __launch_bounds__(256)
void fenwick_attn_kernel(const float* __restrict__ qkv,
                         __half* __restrict__ outA)
{
    const int warp = threadIdx.x >> 5;
    const int lane = threadIdx.x & 31;
    const int t  = blockIdx.x * 8 + warp;
    const int bh = blockIdx.y;
    const int b = bh >> 4;
    const int h = bh & 15;

    const float scale = 0.125f;
    const size_t rowStride = 3 * CH;
    const float* base = qkv + (size_t)b * SEQ * rowStride;

    bool active;
    int myPos;
    if (lane == 0) { myPos = t; active = true; }
    else           { int step = 1 << (lane - 1);
                     myPos = t - step;
                     active = (lane < 12) && (myPos >= 0); }
    if (!active) myPos = t;

    float s = -CUDART_INF_F;
    if (active) {
        const float4* qp4 = (const float4*)(base + (size_t)t * rowStride + h * DH);
        const float4* kp4 = (const float4*)(base + (size_t)myPos * rowStride + CH + h * DH);
        float d = 0.0f;
        #pragma unroll
        for (int i = 0; i < 16; i++) {
            float4 qv = qp4[i];
            float4 kv = kp4[i];
            d += qv.x * kv.x + qv.y * kv.y + qv.z * kv.z + qv.w * kv.w;
        }
        s = d * scale;
    }

    float m = s;
    #pragma unroll
    for (int off = 16; off; off >>= 1) m = fmaxf(m, __shfl_xor_sync(0xFFFFFFFFu, m, off));
    float e = active ? __expf(s - m) : 0.0f;
    float denom = e;
    #pragma unroll
    for (int off = 16; off; off >>= 1) denom += __shfl_xor_sync(0xFFFFFFFFu, denom, off);
    const float inv = 1.0f / denom;

    float o0 = 0.0f, o1 = 0.0f;
    #pragma unroll
    for (int j = 0; j < 12; j++) {
        float ej = __shfl_sync(0xFFFFFFFFu, e, j);
        int   pj = __shfl_sync(0xFFFFFFFFu, myPos, j);
        const float* vp = base + (size_t)pj * rowStride + 2 * CH + h * DH;
        o0 = fmaf(ej, vp[lane], o0);
        o1 = fmaf(ej, vp[lane + 32], o1);
    }
    o0 *= inv;
    o1 *= inv;

    const size_t o = ((size_t)b * SEQ + t) * CH + h * DH;
    outA[o + lane]      = __float2half_rn(o0);
    outA[o + lane + 32] = __float2half_rn(o1);
}

// ---------------------------------------------------------------------------
// Launch
// ---------------------------------------------------------------------------
extern "C" void kernel_launch(void* const* d_in, const int* in_sizes, int n_in,
                              void* d_out, int out_size)
{
    const float* x      = (const float*)d_in[0];
    const float* W_qkv  = (const float*)d_in[1];
    const float* b_qkv  = (const float*)d_in[2];
    const float* W_proj = (const float*)d_in[3];
    const float* b_proj = (const float*)d_in[4];
    float* out = (float*)d_out;

    float *qkv;
    __half *A, *BQ, *BP;
    cudaGetSymbolAddress((void**)&qkv, g_qkv);
    cudaGetSymbolAddress((void**)&A,   g_A);
    cudaGetSymbolAddress((void**)&BQ,  g_BQ);
    cudaGetSymbolAddress((void**)&BP,  g_BP);

    cudaFuncSetAttribute(gemm_fp16_kernel,
                         cudaFuncAttributeMaxDynamicSharedMemorySize, GEMM_SMEM);

    conv_transpose_kernel<<<dim3(3 * CH / 32, CH / 32), 256>>>(W_qkv, BQ, CH, 3 * CH);
    conv_transpose_kernel<<<dim3(CH / 32, CH / 32), 256>>>(W_proj, BP, CH, CH);
    conv_fp16_kernel<<<(MROWS * CH / 4 + 255) / 256, 256>>>(x, A, MROWS * CH / 4);

    // GEMM1: [4096, 3072] = x @ W_qkv + b_qkv
    gemm_fp16_kernel<<<dim3(3 * CH / 128, MROWS / 128), 256, GEMM_SMEM>>>(
        A, BQ, b_qkv, qkv, 3 * CH, CH);

    // Attention, fp16 output (overwrites A)
    fenwick_attn_kernel<<<dim3(SEQ / 8, BATCH * HEADS), 256>>>(qkv, A);

    // GEMM2: [4096, 1024] = att @ W_proj + b_proj
    gemm_fp16_kernel<<<dim3(CH / 128, MROWS / 128), 256, GEMM_SMEM>>>(
        A, BP, b_proj, out, CH, CH);
}